// round 1
// baseline (speedup 1.0000x reference)
#include <cuda_runtime.h>
#include <math.h>

#define GAMMA 3.4f
#define EPS 1e-8f
#define B_DIM 2048
#define P_TOK 197
#define P_USE 196
#define D_DIM 768
#define CHUNK 28   // patches per block (7 chunks * 28 = 196)

__device__ double g_acc;

__global__ void zero_acc_kernel() {
    g_acc = 0.0;
}

__global__ __launch_bounds__(256) void loss_main_kernel(
    const float* __restrict__ patch_tokens,
    const float* __restrict__ out_text,
    const float* __restrict__ gt)
{
    const int b     = blockIdx.x;
    const int chunk = blockIdx.y;
    const int warp  = threadIdx.x >> 5;
    const int lane  = threadIdx.x & 31;

    // Load this batch's out_text row into registers: lane handles float4s
    // at indices lane + 32*j (coalesced), reused for all patches.
    const float4* ot4 = reinterpret_cast<const float4*>(out_text + (size_t)b * D_DIM);
    float4 t[6];
#pragma unroll
    for (int j = 0; j < 6; ++j) t[j] = ot4[lane + 32 * j];

    // out_text norm (per warp, from registers)
    float otn2 = 0.f;
#pragma unroll
    for (int j = 0; j < 6; ++j)
        otn2 += t[j].x * t[j].x + t[j].y * t[j].y + t[j].z * t[j].z + t[j].w * t[j].w;
#pragma unroll
    for (int off = 16; off > 0; off >>= 1)
        otn2 += __shfl_xor_sync(0xffffffffu, otn2, off);
    const float ot_n = fmaxf(sqrtf(otn2), EPS);

    float local = 0.f;

    const int p_base = chunk * CHUNK;
    for (int p = p_base + warp; p < p_base + CHUNK; p += 8) {
        // patch_tokens[b, p+1, :]
        const float4* row = reinterpret_cast<const float4*>(
            patch_tokens + ((size_t)b * P_TOK + (size_t)(p + 1)) * D_DIM);

        float dot = 0.f, nn = 0.f;
#pragma unroll
        for (int j = 0; j < 6; ++j) {
            float4 v = row[lane + 32 * j];
            dot += v.x * t[j].x + v.y * t[j].y + v.z * t[j].z + v.w * t[j].w;
            nn  += v.x * v.x + v.y * v.y + v.z * v.z + v.w * v.w;
        }
#pragma unroll
        for (int off = 16; off > 0; off >>= 1) {
            dot += __shfl_xor_sync(0xffffffffu, dot, off);
            nn  += __shfl_xor_sync(0xffffffffu, nn,  off);
        }

        if (lane == 0) {
            const float pt_n = fmaxf(sqrtf(nn), EPS);
            const float cosv = dot / (pt_n * ot_n);
            // sigmoid(1 - cos)
            const float vec  = 1.0f / (1.0f + expf(cosv - 1.0f));
            const float gtv  = gt[(size_t)b * P_USE + p] * (1.0f / 255.0f);
            const float diff = fabsf(vec - gtv);
            const float term = -logf(1.0f - diff) * (gtv * GAMMA + 1.0f);
            local += term;
        }
    }

    // Block reduction: warp lane0 partials -> smem -> single atomic per block
    __shared__ float warp_sum[8];
    if (lane == 0) warp_sum[warp] = local;
    __syncthreads();
    if (threadIdx.x == 0) {
        float s = 0.f;
#pragma unroll
        for (int w = 0; w < 8; ++w) s += warp_sum[w];
        atomicAdd(&g_acc, (double)s);
    }
}

__global__ void finalize_kernel(float* out) {
    out[0] = (float)(g_acc / (double)B_DIM);
}

extern "C" void kernel_launch(void* const* d_in, const int* in_sizes, int n_in,
                              void* d_out, int out_size) {
    const float* patch_tokens = (const float*)d_in[0];
    const float* out_text     = (const float*)d_in[1];
    const float* gt           = (const float*)d_in[2];
    float* out = (float*)d_out;

    zero_acc_kernel<<<1, 1>>>();
    dim3 grid(B_DIM, P_USE / CHUNK);   // 2048 x 7
    loss_main_kernel<<<grid, 256>>>(patch_tokens, out_text, gt);
    finalize_kernel<<<1, 1>>>(out);
}

// round 2
// speedup vs baseline: 1.1190x; 1.1190x over previous
#include <cuda_runtime.h>
#include <math.h>

#define GAMMA 3.4f
#define EPS 1e-8f
#define B_DIM 2048
#define P_TOK 197
#define P_USE 196
#define D_DIM 768
#define CHUNK 28          // patches per block (7 chunks * 28 = 196)
#define NWARP 7           // 7 warps * 4 patches = 28
#define NBLOCKS (B_DIM * (P_USE / CHUNK))   // 2048*7 = 14336

__device__ double g_acc;              // zero-initialized device globals
__device__ unsigned int g_count;

__global__ __launch_bounds__(NWARP * 32) void loss_fused_kernel(
    const float* __restrict__ patch_tokens,
    const float* __restrict__ out_text,
    const float* __restrict__ gt,
    float* __restrict__ out)
{
    const int b     = blockIdx.x;
    const int chunk = blockIdx.y;
    const int warp  = threadIdx.x >> 5;
    const int lane  = threadIdx.x & 31;

    // out_text[b] into registers, reused across all 4 patches of this warp.
    const float4* ot4 = reinterpret_cast<const float4*>(out_text + (size_t)b * D_DIM);
    float4 t[6];
#pragma unroll
    for (int j = 0; j < 6; ++j) t[j] = __ldg(&ot4[lane + 32 * j]);

    float otn2 = 0.f;
#pragma unroll
    for (int j = 0; j < 6; ++j)
        otn2 += t[j].x * t[j].x + t[j].y * t[j].y + t[j].z * t[j].z + t[j].w * t[j].w;
#pragma unroll
    for (int off = 16; off > 0; off >>= 1)
        otn2 += __shfl_xor_sync(0xffffffffu, otn2, off);
    const float ot_n = fmaxf(sqrtf(otn2), EPS);

    float local = 0.f;
    const int p0 = chunk * CHUNK + warp * 4;   // each warp: exactly 4 consecutive patches

#pragma unroll
    for (int i = 0; i < 4; ++i) {
        const int p = p0 + i;
        const float4* row = reinterpret_cast<const float4*>(
            patch_tokens + ((size_t)b * P_TOK + (size_t)(p + 1)) * D_DIM);

        float dot = 0.f, nn = 0.f;
#pragma unroll
        for (int j = 0; j < 6; ++j) {
            float4 v = __ldcs(&row[lane + 32 * j]);   // streaming: evict-first
            dot += v.x * t[j].x + v.y * t[j].y + v.z * t[j].z + v.w * t[j].w;
            nn  += v.x * v.x + v.y * v.y + v.z * v.z + v.w * v.w;
        }
#pragma unroll
        for (int off = 16; off > 0; off >>= 1) {
            dot += __shfl_xor_sync(0xffffffffu, dot, off);
            nn  += __shfl_xor_sync(0xffffffffu, nn,  off);
        }

        if (lane == 0) {
            const float pt_n = fmaxf(sqrtf(nn), EPS);
            const float cosv = dot / (pt_n * ot_n);
            const float vec  = 1.0f / (1.0f + expf(cosv - 1.0f));   // sigmoid(1-cos)
            const float gtv  = gt[(size_t)b * P_USE + p] * (1.0f / 255.0f);
            const float diff = fabsf(vec - gtv);
            local += -logf(1.0f - diff) * (gtv * GAMMA + 1.0f);
        }
    }

    // Block reduction -> one double atomic per block
    __shared__ float warp_sum[NWARP];
    if (lane == 0) warp_sum[warp] = local;
    __syncthreads();

    if (threadIdx.x == 0) {
        float s = 0.f;
#pragma unroll
        for (int w = 0; w < NWARP; ++w) s += warp_sum[w];
        atomicAdd(&g_acc, (double)s);

        // Last-block finalize: write result, reset accumulators for next replay.
        __threadfence();
        unsigned int arrived = atomicAdd(&g_count, 1u);
        if (arrived == NBLOCKS - 1) {
            double total = atomicAdd(&g_acc, 0.0);   // coherent L2 read
            out[0] = (float)(total / (double)B_DIM);
            g_acc = 0.0;
            g_count = 0u;
        }
    }
}

extern "C" void kernel_launch(void* const* d_in, const int* in_sizes, int n_in,
                              void* d_out, int out_size) {
    const float* patch_tokens = (const float*)d_in[0];
    const float* out_text     = (const float*)d_in[1];
    const float* gt           = (const float*)d_in[2];
    float* out = (float*)d_out;

    dim3 grid(B_DIM, P_USE / CHUNK);   // 2048 x 7
    loss_fused_kernel<<<grid, NWARP * 32>>>(patch_tokens, out_text, gt, out);
}

// round 3
// speedup vs baseline: 1.1232x; 1.0038x over previous
#include <cuda_runtime.h>
#include <math.h>

#define GAMMA 3.4f
#define EPS 1e-8f
#define B_DIM 2048
#define P_TOK 197
#define P_USE 196
#define D_DIM 768
#define NWARP 7
#define NTHREADS (NWARP * 32)      // 224
#define PPW (P_USE / NWARP)        // 28 patches per warp

__device__ double g_acc;           // zero-initialized
__device__ unsigned int g_count;

__global__ __launch_bounds__(NTHREADS, 8) void loss_fused_kernel(
    const float* __restrict__ patch_tokens,
    const float* __restrict__ out_text,
    const float* __restrict__ gt,
    float* __restrict__ out)
{
    __shared__ float4 s_ot[D_DIM / 4];    // 192 float4 = 3KB
    __shared__ float  s_gt[P_USE];
    __shared__ float  s_otn;
    __shared__ float  warp_sum[NWARP];

    const int b    = blockIdx.x;
    const int tid  = threadIdx.x;
    const int warp = tid >> 5;
    const int lane = tid & 31;

    // Stage out_text[b] (192 float4) and gt[b] (196 floats) into smem, coalesced.
    const float4* ot4 = reinterpret_cast<const float4*>(out_text + (size_t)b * D_DIM);
    if (tid < D_DIM / 4) s_ot[tid] = __ldg(&ot4[tid]);
    if (tid < P_USE) s_gt[tid] = __ldg(&gt[(size_t)b * P_USE + tid]);
    __syncthreads();

    // Warp 0 computes ||out_text[b]|| once.
    if (warp == 0) {
        float otn2 = 0.f;
#pragma unroll
        for (int j = 0; j < 6; ++j) {
            float4 q = s_ot[lane + 32 * j];
            otn2 += q.x * q.x + q.y * q.y + q.z * q.z + q.w * q.w;
        }
#pragma unroll
        for (int off = 16; off > 0; off >>= 1)
            otn2 += __shfl_xor_sync(0xffffffffu, otn2, off);
        if (lane == 0) s_otn = fmaxf(sqrtf(otn2), EPS);
    }
    __syncthreads();
    const float ot_n = s_otn;

    float local = 0.f;
    const int p0 = warp * PPW;

    for (int i = 0; i < PPW; ++i) {
        const int p = p0 + i;
        const float4* row = reinterpret_cast<const float4*>(
            patch_tokens + ((size_t)b * P_TOK + (size_t)(p + 1)) * D_DIM);

        float dot = 0.f, nn = 0.f;
#pragma unroll
        for (int j = 0; j < 6; ++j) {
            float4 v = __ldcs(&row[lane + 32 * j]);   // streaming, evict-first
            float4 q = s_ot[lane + 32 * j];
            dot += v.x * q.x + v.y * q.y + v.z * q.z + v.w * q.w;
            nn  += v.x * v.x + v.y * v.y + v.z * v.z + v.w * v.w;
        }
#pragma unroll
        for (int off = 16; off > 0; off >>= 1) {
            dot += __shfl_xor_sync(0xffffffffu, dot, off);
            nn  += __shfl_xor_sync(0xffffffffu, nn,  off);
        }

        if (lane == 0) {
            const float pt_n = fmaxf(sqrtf(nn), EPS);
            const float cosv = dot / (pt_n * ot_n);
            const float vec  = 1.0f / (1.0f + expf(cosv - 1.0f));   // sigmoid(1-cos)
            const float gtv  = s_gt[p] * (1.0f / 255.0f);
            const float diff = fabsf(vec - gtv);
            local += -logf(1.0f - diff) * (gtv * GAMMA + 1.0f);
        }
    }

    if (lane == 0) warp_sum[warp] = local;
    __syncthreads();

    if (tid == 0) {
        float s = 0.f;
#pragma unroll
        for (int w = 0; w < NWARP; ++w) s += warp_sum[w];
        atomicAdd(&g_acc, (double)s);

        __threadfence();
        unsigned int arrived = atomicAdd(&g_count, 1u);
        if (arrived == B_DIM - 1) {
            double total = atomicAdd(&g_acc, 0.0);
            out[0] = (float)(total / (double)B_DIM);
            g_acc = 0.0;
            g_count = 0u;
        }
    }
}

extern "C" void kernel_launch(void* const* d_in, const int* in_sizes, int n_in,
                              void* d_out, int out_size) {
    const float* patch_tokens = (const float*)d_in[0];
    const float* out_text     = (const float*)d_in[1];
    const float* gt           = (const float*)d_in[2];
    float* out = (float*)d_out;

    loss_fused_kernel<<<B_DIM, NTHREADS>>>(patch_tokens, out_text, gt, out);
}

// round 4
// speedup vs baseline: 1.1334x; 1.0090x over previous
#include <cuda_runtime.h>
#include <math.h>

#define GAMMA 3.4f
#define EPS 1e-8f
#define B_DIM 2048
#define P_TOK 197
#define P_USE 196
#define D_DIM 768
#define NWARP 7
#define NTHREADS (NWARP * 32)      // 224
#define PPW (P_USE / NWARP)        // 28 patches per warp

__device__ double g_acc;           // zero-initialized
__device__ unsigned int g_count;

__global__ __launch_bounds__(NTHREADS) void loss_fused_kernel(
    const float* __restrict__ patch_tokens,
    const float* __restrict__ out_text,
    const float* __restrict__ gt,
    float* __restrict__ out)
{
    __shared__ float4 s_ot[D_DIM / 4];    // 192 float4 = 3KB
    __shared__ float  s_gt[P_USE];
    __shared__ float  s_otn;
    __shared__ float  warp_sum[NWARP];

    const int b    = blockIdx.x;
    const int tid  = threadIdx.x;
    const int warp = tid >> 5;
    const int lane = tid & 31;

    // Stage out_text[b] and gt[b] into smem (coalesced).
    const float4* ot4 = reinterpret_cast<const float4*>(out_text + (size_t)b * D_DIM);
    if (tid < D_DIM / 4) s_ot[tid] = __ldg(&ot4[tid]);
    if (tid < P_USE) s_gt[tid] = __ldg(&gt[(size_t)b * P_USE + tid]);
    __syncthreads();

    if (warp == 0) {
        float otn2 = 0.f;
#pragma unroll
        for (int j = 0; j < 6; ++j) {
            float4 q = s_ot[lane + 32 * j];
            otn2 += q.x * q.x + q.y * q.y + q.z * q.z + q.w * q.w;
        }
#pragma unroll
        for (int off = 16; off > 0; off >>= 1)
            otn2 += __shfl_xor_sync(0xffffffffu, otn2, off);
        if (lane == 0) s_otn = fmaxf(sqrtf(otn2), EPS);
    }
    __syncthreads();
    const float ot_n = s_otn;

    float local = 0.f;
    const int p0 = warp * PPW;

    // Software pipeline: keep next row's 6 loads in flight while reducing
    // the current row, so HBM never goes idle during the SHFL chain.
    const float4* row0 = reinterpret_cast<const float4*>(
        patch_tokens + ((size_t)b * P_TOK + (size_t)(p0 + 1)) * D_DIM);
    float4 v[6];
#pragma unroll
    for (int j = 0; j < 6; ++j) v[j] = __ldcs(&row0[lane + 32 * j]);

    for (int i = 0; i < PPW; ++i) {
        const int p = p0 + i;

        // Prefetch next row first (independent of current reduction).
        float4 w[6];
        if (i + 1 < PPW) {
            const float4* rown = reinterpret_cast<const float4*>(
                patch_tokens + ((size_t)b * P_TOK + (size_t)(p + 2)) * D_DIM);
#pragma unroll
            for (int j = 0; j < 6; ++j) w[j] = __ldcs(&rown[lane + 32 * j]);
        }

        float dot = 0.f, nn = 0.f;
#pragma unroll
        for (int j = 0; j < 6; ++j) {
            float4 q = s_ot[lane + 32 * j];
            dot += v[j].x * q.x + v[j].y * q.y + v[j].z * q.z + v[j].w * q.w;
            nn  += v[j].x * v[j].x + v[j].y * v[j].y + v[j].z * v[j].z + v[j].w * v[j].w;
        }
#pragma unroll
        for (int off = 16; off > 0; off >>= 1) {
            dot += __shfl_xor_sync(0xffffffffu, dot, off);
            nn  += __shfl_xor_sync(0xffffffffu, nn,  off);
        }

        if (lane == 0) {
            const float pt_n = fmaxf(sqrtf(nn), EPS);
            const float cosv = dot / (pt_n * ot_n);
            const float vec  = 1.0f / (1.0f + expf(cosv - 1.0f));   // sigmoid(1-cos)
            const float gtv  = s_gt[p] * (1.0f / 255.0f);
            const float diff = fabsf(vec - gtv);
            local += -logf(1.0f - diff) * (gtv * GAMMA + 1.0f);
        }

#pragma unroll
        for (int j = 0; j < 6; ++j) v[j] = w[j];
    }

    if (lane == 0) warp_sum[warp] = local;
    __syncthreads();

    if (tid == 0) {
        float s = 0.f;
#pragma unroll
        for (int w2 = 0; w2 < NWARP; ++w2) s += warp_sum[w2];
        atomicAdd(&g_acc, (double)s);

        __threadfence();
        unsigned int arrived = atomicAdd(&g_count, 1u);
        if (arrived == B_DIM - 1) {
            double total = atomicAdd(&g_acc, 0.0);
            out[0] = (float)(total / (double)B_DIM);
            g_acc = 0.0;
            g_count = 0u;
        }
    }
}

extern "C" void kernel_launch(void* const* d_in, const int* in_sizes, int n_in,
                              void* d_out, int out_size) {
    const float* patch_tokens = (const float*)d_in[0];
    const float* out_text     = (const float*)d_in[1];
    const float* gt           = (const float*)d_in[2];
    float* out = (float*)d_out;

    loss_fused_kernel<<<B_DIM, NTHREADS>>>(patch_tokens, out_text, gt, out);
}